// round 7
// baseline (speedup 1.0000x reference)
#include <cuda_runtime.h>
#include <cuda_fp16.h>
#include <cstdint>

#define BB 16
#define CC 128
#define HH 128
#define WW 128
#define SDIM 512
#define PCW 130              // padded width in gmem NHWC layout
#define XROWB 64             // bytes per px per 32-ci chunk (32 * half)
#define PITCH 80             // smem pitch per px/cout row (64B data + 16B pad)

// smem layout (bytes)
#define SB_ROW (PCW * PITCH)         // 10400 per strip row
#define SB_HL  (3 * SB_ROW)          // 31200 per hi/lo strip
#define OFF_SA (2 * SB_HL)           // 62400
#define SA_HL  (128 * PITCH)         // 10240
#define SA_BUF (2 * SA_HL)           // 20480
#define SMEMSZ (OFF_SA + 2 * SA_BUF) // 103360

// device scratch (allocation-free rule)
__device__ __half g_xh[(size_t)BB * 4 * HH * PCW * 32];
__device__ __half g_xl[(size_t)BB * 4 * HH * PCW * 32];
__device__ __half g_wh[(size_t)BB * 4 * 9 * 128 * 32];
__device__ __half g_wl[(size_t)BB * 4 * 9 * 128 * 32];
__device__ float  g_s[BB * CC];

// ---- helpers ----
static __device__ __forceinline__ uint32_t smem_u32(const void* p){
    uint32_t a; asm("{ .reg .u64 t; cvta.to.shared.u64 t, %1; cvt.u32.u64 %0, t; }":"=r"(a):"l"(p)); return a; }
static __device__ __forceinline__ void cp16(uint32_t d, const void* s, uint32_t sz){
    asm volatile("cp.async.cg.shared.global [%0], [%1], 16, %2;"::"r"(d),"l"(s),"r"(sz)); }
static __device__ __forceinline__ void cp_commit(){ asm volatile("cp.async.commit_group;"); }
static __device__ __forceinline__ void cp_wait1(){ asm volatile("cp.async.wait_group 1;":::"memory"); }
static __device__ __forceinline__ void cp_wait0(){ asm volatile("cp.async.wait_group 0;":::"memory"); }
static __device__ __forceinline__ void ldm4(uint32_t* r, uint32_t addr){
    asm volatile("ldmatrix.sync.aligned.m8n8.x4.shared.b16 {%0,%1,%2,%3}, [%4];"
                 : "=r"(r[0]),"=r"(r[1]),"=r"(r[2]),"=r"(r[3]) : "r"(addr)); }
static __device__ __forceinline__ void mma16816(float* c, const uint32_t* a, uint32_t b0, uint32_t b1){
    asm volatile("mma.sync.aligned.m16n8k16.row.col.f32.f16.f16.f32 "
                 "{%0,%1,%2,%3},{%4,%5,%6,%7},{%8,%9},{%0,%1,%2,%3};"
                 : "+f"(c[0]),"+f"(c[1]),"+f"(c[2]),"+f"(c[3])
                 : "r"(a[0]),"r"(a[1]),"r"(a[2]),"r"(a[3]),"r"(b0),"r"(b1)); }

// ---------------- kernel 1: modulation scalars ----------------
__global__ void modulate_kernel(const float* __restrict__ style, const float* __restrict__ mod_w,
                                const float* __restrict__ mod_b){
    const int gw = blockIdx.x*8 + (threadIdx.x>>5), lane = threadIdx.x&31;
    const int b = gw>>7, i = gw&127;
    const float* st = style + b*SDIM;
    const float* mw = mod_w + i*SDIM;
    float acc = 0.f;
#pragma unroll
    for (int d = 0; d < SDIM/32; d++) acc += st[d*32+lane]*mw[d*32+lane];
#pragma unroll
    for (int o = 16; o > 0; o >>= 1) acc += __shfl_xor_sync(~0u, acc, o);
    if (lane==0) g_s[b*CC+i] = acc*0.044194173824159216f + mod_b[i];
}

// ---------------- kernel 2: weights -> fp16 hi/lo, [b][chunk][tap][cout][ci32] ----------------
__global__ void weight_kernel(const float* __restrict__ weight){
    const int o = blockIdx.x, b = blockIdx.y, i = threadIdx.x;
    const float s = g_s[b*CC+i] * 0.029462782549439483f;  // 1/sqrt(1152)
    float wm[9]; float sq = 0.f;
#pragma unroll
    for (int t = 0; t < 9; t++){ float w = weight[(o*CC+i)*9+t]*s; wm[t]=w; sq += w*w; }
    __shared__ float red[4];
#pragma unroll
    for (int off = 16; off > 0; off >>= 1) sq += __shfl_xor_sync(~0u, sq, off);
    if ((i&31)==0) red[i>>5]=sq;
    __syncthreads();
    const float demod = rsqrtf(red[0]+red[1]+red[2]+red[3]+1e-8f);
#pragma unroll
    for (int t = 0; t < 9; t++){
        float w = wm[t]*demod;
        __half h = __float2half_rn(w);
        __half l = __float2half_rn(w - __half2float(h));
        size_t di = (((size_t)((b*4 + (i>>5))*9 + t))*128 + o)*32 + (i&31);
        g_wh[di]=h; g_wl[di]=l;
    }
}

// ---------------- kernel 3: x NCHW fp32 -> padded NHWC fp16 hi/lo ----------------
__global__ void convert_kernel(const float* __restrict__ x){
    __shared__ float tile[64][129];
    const int y = blockIdx.x, b = blockIdx.y, tid = threadIdx.x;
    {   // zero pad columns px=0 and px=129 for all 4 chunks
        int ch = tid>>6, pc = ((tid>>5)&1) ? 129 : 0, ci = tid&31;
        size_t di = (((size_t)((b*4+ch)*HH + y))*PCW + pc)*32 + ci;
        g_xh[di] = __float2half_rn(0.f); g_xl[di] = __float2half_rn(0.f);
    }
#pragma unroll
    for (int half_ = 0; half_ < 2; half_++){
        __syncthreads();
        for (int e = tid; e < 64*128; e += 256){
            int ci = e>>7, c = e&127;
            tile[ci][c] = x[(((size_t)(b*CC + half_*64 + ci))*HH + y)*WW + c];
        }
        __syncthreads();
        for (int e = tid; e < 128*64; e += 256){
            int c = e>>6, cil = e&63;
            float v = tile[cil][c];
            __half h = __float2half_rn(v);
            __half l = __float2half_rn(v - __half2float(h));
            int ch = half_*2 + (cil>>5);
            size_t di = (((size_t)((b*4+ch)*HH + y))*PCW + (c+1))*32 + (cil&31);
            g_xh[di]=h; g_xl[di]=l;
        }
    }
}

// ---------------- kernel 4: conv via mma.sync, 4 warps x (64x64) warp tiles ----------------
__global__ void __launch_bounds__(128, 2) conv_kernel(float* __restrict__ out){
    extern __shared__ __align__(1024) char sm[];
    const uint32_t sb = smem_u32(sm);
    const int b = blockIdx.y, y = blockIdx.x;
    const int tid = threadIdx.x, wid = tid>>5, lane = tid&31;
    const int m0 = (wid&1)*64, n0 = (wid>>1)*64;
    const int row_off = lane & 15;                    // ldmatrix row selector
    const int kb16 = ((lane>>4)&1)*16;                // k-half selector (bytes)

    float acc[4][8][4];
#pragma unroll
    for (int mt=0; mt<4; mt++)
#pragma unroll
        for (int nt=0; nt<8; nt++)
#pragma unroll
            for (int j=0; j<4; j++) acc[mt][nt][j] = 0.f;

    const char* gx[2] = {(const char*)g_xh, (const char*)g_xl};
    const char* gw[2] = {(const char*)g_wh, (const char*)g_wl};

#pragma unroll 1
    for (int ch = 0; ch < 4; ch++){
        // ---- stage B strip (3 rows x 130 px, hi+lo) + A tap0 into buf0 ----
        for (int e = tid; e < 3120; e += 128){
            int hl = e / 1560, rem = e % 1560;
            int row = rem / 520, q = rem % 520;
            int px = q >> 2, c = q & 3;
            int gy = y - 1 + row;
            uint32_t val = (gy >= 0 && gy < HH) ? 16u : 0u;
            int gyc = gy < 0 ? 0 : (gy > 127 ? 127 : gy);
            const char* src = gx[hl] + ((((size_t)(b*4+ch)*HH + gyc)*PCW + px)*XROWB) + c*16;
            cp16(sb + hl*SB_HL + row*SB_ROW + px*PITCH + c*16, src, val);
        }
        for (int e = tid; e < 1024; e += 128){
            int hl = e >> 9, rem = e & 511;
            int co = rem >> 2, c = rem & 3;
            const char* src = gw[hl] + (((size_t)((b*4+ch)*9 + 0))*4096 + co*32)*2 + c*16;
            cp16(sb + OFF_SA + hl*SA_HL + co*PITCH + c*16, src, 16);
        }
        cp_commit();

#pragma unroll 1
        for (int tap = 0; tap < 9; tap++){
            const int ky = tap / 3, kx = tap % 3;
            const int buf = tap & 1;
            if (tap < 8){
                const int nb = (tap+1) & 1;
                for (int e = tid; e < 1024; e += 128){
                    int hl = e >> 9, rem = e & 511;
                    int co = rem >> 2, c = rem & 3;
                    const char* src = gw[hl] + (((size_t)((b*4+ch)*9 + tap+1))*4096 + co*32)*2 + c*16;
                    cp16(sb + OFF_SA + nb*SA_BUF + hl*SA_HL + co*PITCH + c*16, src, 16);
                }
                cp_commit();
                cp_wait1();
            } else {
                cp_wait0();
            }
            __syncthreads();

#pragma unroll
            for (int ks = 0; ks < 2; ks++){
                // ---- hoisted fragment loads: hi+lo of A and B, loaded ONCE per ks ----
                uint32_t a[2][4][4];   // [hl][mt][4]
#pragma unroll
                for (int hl = 0; hl < 2; hl++)
#pragma unroll
                    for (int mt = 0; mt < 4; mt++)
                        ldm4(a[hl][mt], sb + OFF_SA + buf*SA_BUF + hl*SA_HL
                                        + (m0 + mt*16 + row_off)*PITCH + ks*32 + kb16);
                uint32_t bf[2][4][4];  // [hl][np][4]
#pragma unroll
                for (int hl = 0; hl < 2; hl++)
#pragma unroll
                    for (int np = 0; np < 4; np++)
                        ldm4(bf[hl][np], sb + hl*SB_HL + ky*SB_ROW
                                         + (n0 + np*16 + kx + row_off)*PITCH + ks*32 + kb16);
                // B x4 gives {nLo/kLo, nHi/kLo, nLo/kHi, nHi/kHi}: pair (r0,r2),(r1,r3)
#pragma unroll
                for (int mt = 0; mt < 4; mt++)
#pragma unroll
                    for (int np = 0; np < 4; np++){
                        mma16816(acc[mt][np*2+0], a[0][mt], bf[0][np][0], bf[0][np][2]); // wh*xh
                        mma16816(acc[mt][np*2+1], a[0][mt], bf[0][np][1], bf[0][np][3]);
                        mma16816(acc[mt][np*2+0], a[0][mt], bf[1][np][0], bf[1][np][2]); // wh*xl
                        mma16816(acc[mt][np*2+1], a[0][mt], bf[1][np][1], bf[1][np][3]);
                        mma16816(acc[mt][np*2+0], a[1][mt], bf[0][np][0], bf[0][np][2]); // wl*xh
                        mma16816(acc[mt][np*2+1], a[1][mt], bf[0][np][1], bf[0][np][3]);
                    }
            }
            __syncthreads();
        }
    }

    // ---- epilogue ----
#pragma unroll
    for (int mt = 0; mt < 4; mt++)
#pragma unroll
        for (int nt = 0; nt < 8; nt++){
            int m = m0 + mt*16 + (lane>>2);
            int n = n0 + nt*8 + (lane&3)*2;
            float* p = out + (((size_t)(b*CC + m))*HH + y)*WW + n;
            *(float2*)p = make_float2(acc[mt][nt][0], acc[mt][nt][1]);
            *(float2*)(p + (size_t)8*HH*WW) = make_float2(acc[mt][nt][2], acc[mt][nt][3]);
        }
}

// ---------------------------------------------------------------------------
extern "C" void kernel_launch(void* const* d_in, const int* in_sizes, int n_in,
                              void* d_out, int out_size){
    const float* x      = (const float*)d_in[0];
    const float* style  = (const float*)d_in[1];
    const float* weight = (const float*)d_in[2];
    const float* mod_w  = (const float*)d_in[3];
    const float* mod_b  = (const float*)d_in[4];
    float* out = (float*)d_out;

    cudaFuncSetAttribute(conv_kernel, cudaFuncAttributeMaxDynamicSharedMemorySize, SMEMSZ);

    modulate_kernel<<<BB*CC/8, 256>>>(style, mod_w, mod_b);
    weight_kernel<<<dim3(CC, BB), CC>>>(weight);
    convert_kernel<<<dim3(HH, BB), 256>>>(x);
    conv_kernel<<<dim3(HH, BB), 128, SMEMSZ>>>(out);
}

// round 8
// speedup vs baseline: 2.2660x; 2.2660x over previous
#include <cuda_runtime.h>
#include <cuda_fp16.h>
#include <cstdint>

#define BB 16
#define CC 128
#define HH 128
#define WW 128
#define SDIM 512
#define PCW 130              // padded width in gmem NHWC layout
#define XROWB 64             // bytes per px per 32-ci chunk (32 * half)
#define PITCH 80             // smem pitch per px/cout row (64B data + 16B pad)

// smem layout (bytes)
#define SB_ROW (PCW * PITCH)          // 10400 per strip row
#define OFF_SA (3 * SB_ROW)           // 31200 (B strip = 3 rows)
#define SA_TAP (128 * PITCH)          // 10240 per tap
#define SMEMSZ (OFF_SA + 2 * SA_TAP)  // 51680

// device scratch (allocation-free rule)
__device__ __half g_x[(size_t)BB * 4 * HH * PCW * 32];   // NHWC fp16, padded W
__device__ __half g_w[(size_t)BB * 4 * 9 * 128 * 32];    // [b][chunk][tap][cout][ci32]
__device__ float  g_s[BB * CC];

// ---- helpers ----
static __device__ __forceinline__ uint32_t smem_u32(const void* p){
    uint32_t a; asm("{ .reg .u64 t; cvta.to.shared.u64 t, %1; cvt.u32.u64 %0, t; }":"=r"(a):"l"(p)); return a; }
static __device__ __forceinline__ void cp16(uint32_t d, const void* s, uint32_t sz){
    asm volatile("cp.async.cg.shared.global [%0], [%1], 16, %2;"::"r"(d),"l"(s),"r"(sz)); }
static __device__ __forceinline__ void cp_commit(){ asm volatile("cp.async.commit_group;"); }
static __device__ __forceinline__ void cp_wait1(){ asm volatile("cp.async.wait_group 1;":::"memory"); }
static __device__ __forceinline__ void cp_wait0(){ asm volatile("cp.async.wait_group 0;":::"memory"); }
static __device__ __forceinline__ void ldm4(uint32_t* r, uint32_t addr){
    asm volatile("ldmatrix.sync.aligned.m8n8.x4.shared.b16 {%0,%1,%2,%3}, [%4];"
                 : "=r"(r[0]),"=r"(r[1]),"=r"(r[2]),"=r"(r[3]) : "r"(addr)); }
static __device__ __forceinline__ void mma16816(float* c, const uint32_t* a, uint32_t b0, uint32_t b1){
    asm volatile("mma.sync.aligned.m16n8k16.row.col.f32.f16.f16.f32 "
                 "{%0,%1,%2,%3},{%4,%5,%6,%7},{%8,%9},{%0,%1,%2,%3};"
                 : "+f"(c[0]),"+f"(c[1]),"+f"(c[2]),"+f"(c[3])
                 : "r"(a[0]),"r"(a[1]),"r"(a[2]),"r"(a[3]),"r"(b0),"r"(b1)); }

// ---------------- kernel 1: modulation scalars ----------------
__global__ void modulate_kernel(const float* __restrict__ style, const float* __restrict__ mod_w,
                                const float* __restrict__ mod_b){
    const int gw = blockIdx.x*8 + (threadIdx.x>>5), lane = threadIdx.x&31;
    const int b = gw>>7, i = gw&127;
    const float* st = style + b*SDIM;
    const float* mw = mod_w + i*SDIM;
    float acc = 0.f;
#pragma unroll
    for (int d = 0; d < SDIM/32; d++) acc += st[d*32+lane]*mw[d*32+lane];
#pragma unroll
    for (int o = 16; o > 0; o >>= 1) acc += __shfl_xor_sync(~0u, acc, o);
    if (lane==0) g_s[b*CC+i] = acc*0.044194173824159216f + mod_b[i];
}

// ---------------- kernel 2: weights -> fp16, [b][chunk][tap][cout][ci32] ----------------
__global__ void weight_kernel(const float* __restrict__ weight){
    const int o = blockIdx.x, b = blockIdx.y, i = threadIdx.x;
    const float s = g_s[b*CC+i] * 0.029462782549439483f;  // 1/sqrt(1152)
    float wm[9]; float sq = 0.f;
#pragma unroll
    for (int t = 0; t < 9; t++){ float w = weight[(o*CC+i)*9+t]*s; wm[t]=w; sq += w*w; }
    __shared__ float red[4];
#pragma unroll
    for (int off = 16; off > 0; off >>= 1) sq += __shfl_xor_sync(~0u, sq, off);
    if ((i&31)==0) red[i>>5]=sq;
    __syncthreads();
    const float demod = rsqrtf(red[0]+red[1]+red[2]+red[3]+1e-8f);
#pragma unroll
    for (int t = 0; t < 9; t++){
        size_t di = (((size_t)((b*4 + (i>>5))*9 + t))*128 + o)*32 + (i&31);
        g_w[di] = __float2half_rn(wm[t]*demod);
    }
}

// ---------------- kernel 3: x NCHW fp32 -> padded NHWC fp16 ----------------
__global__ void convert_kernel(const float* __restrict__ x){
    __shared__ float tile[64][129];
    const int y = blockIdx.x, b = blockIdx.y, tid = threadIdx.x;
    {   // zero pad columns px=0 and px=129 for all 4 chunks
        int ch = tid>>6, pc = ((tid>>5)&1) ? 129 : 0, ci = tid&31;
        size_t di = (((size_t)((b*4+ch)*HH + y))*PCW + pc)*32 + ci;
        g_x[di] = __float2half_rn(0.f);
    }
#pragma unroll
    for (int half_ = 0; half_ < 2; half_++){
        __syncthreads();
        for (int e = tid; e < 64*128; e += 256){
            int ci = e>>7, c = e&127;
            tile[ci][c] = x[(((size_t)(b*CC + half_*64 + ci))*HH + y)*WW + c];
        }
        __syncthreads();
        for (int e = tid; e < 128*64; e += 256){
            int c = e>>6, cil = e&63;
            int ch = half_*2 + (cil>>5);
            size_t di = (((size_t)((b*4+ch)*HH + y))*PCW + (c+1))*32 + (cil&31);
            g_x[di] = __float2half_rn(tile[cil][c]);
        }
    }
}

// ---------------- kernel 4: conv via mma.sync, 8 warps x (32x64) warp tiles ----------------
__global__ void __launch_bounds__(256, 2) conv_kernel(float* __restrict__ out){
    extern __shared__ __align__(1024) char sm[];
    const uint32_t sb = smem_u32(sm);
    const int b = blockIdx.y, y = blockIdx.x;
    const int tid = threadIdx.x, wid = tid>>5, lane = tid&31;
    const int m0 = (wid&3)*32, n0 = (wid>>2)*64;
    const int row_off = lane & 15;                    // ldmatrix row selector
    const int kb16 = ((lane>>4)&1)*16;                // k-half selector (bytes)

    float acc[2][8][4];
#pragma unroll
    for (int mt=0; mt<2; mt++)
#pragma unroll
        for (int nt=0; nt<8; nt++)
#pragma unroll
            for (int j=0; j<4; j++) acc[mt][nt][j] = 0.f;

#pragma unroll 1
    for (int ch = 0; ch < 4; ch++){
        // ---- stage B strip (3 rows x 130 px) + A tap0 into buf0 ----
        for (int e = tid; e < 1560; e += 256){
            int row = e / 520, q = e % 520;
            int px = q >> 2, c = q & 3;
            int gy = y - 1 + row;
            uint32_t val = (gy >= 0 && gy < HH) ? 16u : 0u;
            int gyc = gy < 0 ? 0 : (gy > 127 ? 127 : gy);
            const char* src = (const char*)g_x + ((((size_t)(b*4+ch)*HH + gyc)*PCW + px)*XROWB) + c*16;
            cp16(sb + row*SB_ROW + px*PITCH + c*16, src, val);
        }
        for (int e = tid; e < 512; e += 256){
            int co = e >> 2, c = e & 3;
            const char* src = (const char*)g_w + (((size_t)((b*4+ch)*9 + 0))*4096 + co*32)*2 + c*16;
            cp16(sb + OFF_SA + co*PITCH + c*16, src, 16);
        }
        cp_commit();

#pragma unroll 1
        for (int tap = 0; tap < 9; tap++){
            const int ky = tap / 3, kx = tap % 3;
            const int buf = tap & 1;
            if (tap < 8){
                const int nb = (tap+1) & 1;
                for (int e = tid; e < 512; e += 256){
                    int co = e >> 2, c = e & 3;
                    const char* src = (const char*)g_w + (((size_t)((b*4+ch)*9 + tap+1))*4096 + co*32)*2 + c*16;
                    cp16(sb + OFF_SA + nb*SA_TAP + co*PITCH + c*16, src, 16);
                }
                cp_commit();
                cp_wait1();
            } else {
                cp_wait0();
            }
            __syncthreads();

#pragma unroll
            for (int ks = 0; ks < 2; ks++){
                uint32_t a[2][4];
#pragma unroll
                for (int mt = 0; mt < 2; mt++)
                    ldm4(a[mt], sb + OFF_SA + buf*SA_TAP
                                + (m0 + mt*16 + row_off)*PITCH + ks*32 + kb16);
                uint32_t bf[4][4];
#pragma unroll
                for (int np = 0; np < 4; np++)
                    ldm4(bf[np], sb + ky*SB_ROW
                                 + (n0 + np*16 + kx + row_off)*PITCH + ks*32 + kb16);
                // B x4 gives {nLo/kLo, nHi/kLo, nLo/kHi, nHi/kHi}: pair (r0,r2),(r1,r3)
#pragma unroll
                for (int mt = 0; mt < 2; mt++)
#pragma unroll
                    for (int np = 0; np < 4; np++){
                        mma16816(acc[mt][np*2+0], a[mt], bf[np][0], bf[np][2]);
                        mma16816(acc[mt][np*2+1], a[mt], bf[np][1], bf[np][3]);
                    }
            }
            __syncthreads();
        }
    }

    // ---- epilogue ----
#pragma unroll
    for (int mt = 0; mt < 2; mt++)
#pragma unroll
        for (int nt = 0; nt < 8; nt++){
            int m = m0 + mt*16 + (lane>>2);
            int n = n0 + nt*8 + (lane&3)*2;
            float* p = out + (((size_t)(b*CC + m))*HH + y)*WW + n;
            *(float2*)p = make_float2(acc[mt][nt][0], acc[mt][nt][1]);
            *(float2*)(p + (size_t)8*HH*WW) = make_float2(acc[mt][nt][2], acc[mt][nt][3]);
        }
}

// ---------------------------------------------------------------------------
extern "C" void kernel_launch(void* const* d_in, const int* in_sizes, int n_in,
                              void* d_out, int out_size){
    const float* x      = (const float*)d_in[0];
    const float* style  = (const float*)d_in[1];
    const float* weight = (const float*)d_in[2];
    const float* mod_w  = (const float*)d_in[3];
    const float* mod_b  = (const float*)d_in[4];
    float* out = (float*)d_out;

    cudaFuncSetAttribute(conv_kernel, cudaFuncAttributeMaxDynamicSharedMemorySize, SMEMSZ);

    modulate_kernel<<<BB*CC/8, 256>>>(style, mod_w, mod_b);
    weight_kernel<<<dim3(CC, BB), CC>>>(weight);
    convert_kernel<<<dim3(HH, BB), 256>>>(x);
    conv_kernel<<<dim3(HH, BB), 256, SMEMSZ>>>(out);
}

// round 9
// speedup vs baseline: 2.3958x; 1.0573x over previous
#include <cuda_runtime.h>
#include <cuda_fp16.h>
#include <cstdint>

#define BB 16
#define CC 128
#define HH 128
#define WW 128
#define SDIM 512
#define PCW 130              // padded width in gmem NHWC layout
#define XROWB 64             // bytes per px per 32-ci chunk (32 * half)
#define PITCH 80             // smem pitch per px/cout row (64B data + 16B pad)

// smem layout (bytes)
#define SB_ROW (PCW * PITCH)          // 10400 per strip row
#define OFF_SA (3 * SB_ROW)           // 31200 (B strip = 3 rows)
#define SA_TAP (128 * PITCH)          // 10240 per tap
#define SA_KY  (3 * SA_TAP)           // 30720 per ky group (3 kx taps)
#define SMEMSZ (OFF_SA + 2 * SA_KY)   // 92640

// device scratch (allocation-free rule)
__device__ __half g_x[(size_t)BB * 4 * HH * PCW * 32];   // NHWC fp16, padded W
__device__ __half g_w[(size_t)BB * 4 * 9 * 128 * 32];    // [b][chunk][tap][cout][ci32]
__device__ float  g_s[BB * CC];

// ---- helpers ----
static __device__ __forceinline__ uint32_t smem_u32(const void* p){
    uint32_t a; asm("{ .reg .u64 t; cvta.to.shared.u64 t, %1; cvt.u32.u64 %0, t; }":"=r"(a):"l"(p)); return a; }
static __device__ __forceinline__ void cp16(uint32_t d, const void* s, uint32_t sz){
    asm volatile("cp.async.cg.shared.global [%0], [%1], 16, %2;"::"r"(d),"l"(s),"r"(sz)); }
static __device__ __forceinline__ void cp_commit(){ asm volatile("cp.async.commit_group;"); }
static __device__ __forceinline__ void cp_wait1(){ asm volatile("cp.async.wait_group 1;":::"memory"); }
static __device__ __forceinline__ void cp_wait0(){ asm volatile("cp.async.wait_group 0;":::"memory"); }
static __device__ __forceinline__ void ldm4(uint32_t* r, uint32_t addr){
    asm volatile("ldmatrix.sync.aligned.m8n8.x4.shared.b16 {%0,%1,%2,%3}, [%4];"
                 : "=r"(r[0]),"=r"(r[1]),"=r"(r[2]),"=r"(r[3]) : "r"(addr)); }
static __device__ __forceinline__ void mma16816(float* c, const uint32_t* a, uint32_t b0, uint32_t b1){
    asm volatile("mma.sync.aligned.m16n8k16.row.col.f32.f16.f16.f32 "
                 "{%0,%1,%2,%3},{%4,%5,%6,%7},{%8,%9},{%0,%1,%2,%3};"
                 : "+f"(c[0]),"+f"(c[1]),"+f"(c[2]),"+f"(c[3])
                 : "r"(a[0]),"r"(a[1]),"r"(a[2]),"r"(a[3]),"r"(b0),"r"(b1)); }

// ---------------- kernel 1: modulation scalars ----------------
__global__ void modulate_kernel(const float* __restrict__ style, const float* __restrict__ mod_w,
                                const float* __restrict__ mod_b){
    const int gw = blockIdx.x*8 + (threadIdx.x>>5), lane = threadIdx.x&31;
    const int b = gw>>7, i = gw&127;
    const float* st = style + b*SDIM;
    const float* mw = mod_w + i*SDIM;
    float acc = 0.f;
#pragma unroll
    for (int d = 0; d < SDIM/32; d++) acc += st[d*32+lane]*mw[d*32+lane];
#pragma unroll
    for (int o = 16; o > 0; o >>= 1) acc += __shfl_xor_sync(~0u, acc, o);
    if (lane==0) g_s[b*CC+i] = acc*0.044194173824159216f + mod_b[i];
}

// ---------------- kernel 2: weights -> fp16, [b][chunk][tap][cout][ci32] ----------------
__global__ void weight_kernel(const float* __restrict__ weight){
    const int o = blockIdx.x, b = blockIdx.y, i = threadIdx.x;
    const float s = g_s[b*CC+i] * 0.029462782549439483f;  // 1/sqrt(1152)
    float wm[9]; float sq = 0.f;
#pragma unroll
    for (int t = 0; t < 9; t++){ float w = weight[(o*CC+i)*9+t]*s; wm[t]=w; sq += w*w; }
    __shared__ float red[4];
#pragma unroll
    for (int off = 16; off > 0; off >>= 1) sq += __shfl_xor_sync(~0u, sq, off);
    if ((i&31)==0) red[i>>5]=sq;
    __syncthreads();
    const float demod = rsqrtf(red[0]+red[1]+red[2]+red[3]+1e-8f);
#pragma unroll
    for (int t = 0; t < 9; t++){
        size_t di = (((size_t)((b*4 + (i>>5))*9 + t))*128 + o)*32 + (i&31);
        g_w[di] = __float2half_rn(wm[t]*demod);
    }
}

// ---------------- kernel 3: x NCHW fp32 -> padded NHWC fp16 ----------------
__global__ void convert_kernel(const float* __restrict__ x){
    __shared__ float tile[64][129];
    const int y = blockIdx.x, b = blockIdx.y, tid = threadIdx.x;
    {   // zero pad columns px=0 and px=129 for all 4 chunks
        int ch = tid>>6, pc = ((tid>>5)&1) ? 129 : 0, ci = tid&31;
        size_t di = (((size_t)((b*4+ch)*HH + y))*PCW + pc)*32 + ci;
        g_x[di] = __float2half_rn(0.f);
    }
#pragma unroll
    for (int half_ = 0; half_ < 2; half_++){
        __syncthreads();
        for (int e = tid; e < 64*128; e += 256){
            int ci = e>>7, c = e&127;
            tile[ci][c] = x[(((size_t)(b*CC + half_*64 + ci))*HH + y)*WW + c];
        }
        __syncthreads();
        for (int e = tid; e < 128*64; e += 256){
            int c = e>>6, cil = e&63;
            int ch = half_*2 + (cil>>5);
            size_t di = (((size_t)((b*4+ch)*HH + y))*PCW + (c+1))*32 + (cil&31);
            g_x[di] = __float2half_rn(tile[cil][c]);
        }
    }
}

// ---------------- kernel 4: conv via mma.sync, per-ky A staging ----------------
__global__ void __launch_bounds__(256, 2) conv_kernel(float* __restrict__ out){
    extern __shared__ __align__(1024) char sm[];
    const uint32_t sb = smem_u32(sm);
    const int b = blockIdx.y, y = blockIdx.x;
    const int tid = threadIdx.x, wid = tid>>5, lane = tid&31;
    const int m0 = (wid&3)*32, n0 = (wid>>2)*64;
    const int row_off = lane & 15;                    // ldmatrix row selector
    const int kb16 = ((lane>>4)&1)*16;                // k-half selector (bytes)

    float acc[2][8][4];
#pragma unroll
    for (int mt=0; mt<2; mt++)
#pragma unroll
        for (int nt=0; nt<8; nt++)
#pragma unroll
            for (int j=0; j<4; j++) acc[mt][nt][j] = 0.f;

#pragma unroll 1
    for (int ch = 0; ch < 4; ch++){
        // ---- group g0: B strip (3 rows x 130 px) + A(ky=0) all 3 kx ----
        for (int e = tid; e < 1560; e += 256){
            int row = e / 520, q = e % 520;
            int px = q >> 2, c = q & 3;
            int gy = y - 1 + row;
            uint32_t val = (gy >= 0 && gy < HH) ? 16u : 0u;
            int gyc = gy < 0 ? 0 : (gy > 127 ? 127 : gy);
            const char* src = (const char*)g_x + ((((size_t)(b*4+ch)*HH + gyc)*PCW + px)*XROWB) + c*16;
            cp16(sb + row*SB_ROW + px*PITCH + c*16, src, val);
        }
        for (int e = tid; e < 1536; e += 256){
            int kx = e / 512, rem = e % 512;
            int co = rem >> 2, c = rem & 3;
            const char* src = (const char*)g_w + (((size_t)((b*4+ch)*9 + kx))*4096 + co*32)*2 + c*16;
            cp16(sb + OFF_SA + kx*SA_TAP + co*PITCH + c*16, src, 16);
        }
        cp_commit();

#pragma unroll 1
        for (int ky = 0; ky < 3; ky++){
            const int buf = ky & 1;
            if (ky < 2){
                const int nb = (ky+1) & 1;
                for (int e = tid; e < 1536; e += 256){
                    int kx = e / 512, rem = e % 512;
                    int co = rem >> 2, c = rem & 3;
                    const char* src = (const char*)g_w
                        + (((size_t)((b*4+ch)*9 + (ky+1)*3 + kx))*4096 + co*32)*2 + c*16;
                    cp16(sb + OFF_SA + nb*SA_KY + kx*SA_TAP + co*PITCH + c*16, src, 16);
                }
                cp_commit();
                cp_wait1();
            } else {
                cp_wait0();
            }
            __syncthreads();

#pragma unroll
            for (int ks = 0; ks < 2; ks++){
#pragma unroll
                for (int kx = 0; kx < 3; kx++){
                    uint32_t a[2][4];
#pragma unroll
                    for (int mt = 0; mt < 2; mt++)
                        ldm4(a[mt], sb + OFF_SA + buf*SA_KY + kx*SA_TAP
                                    + (m0 + mt*16 + row_off)*PITCH + ks*32 + kb16);
                    uint32_t bf[4][4];
#pragma unroll
                    for (int np = 0; np < 4; np++)
                        ldm4(bf[np], sb + ky*SB_ROW
                                     + (n0 + np*16 + kx + row_off)*PITCH + ks*32 + kb16);
                    // B x4 gives {nLo/kLo, nHi/kLo, nLo/kHi, nHi/kHi}: pair (r0,r2),(r1,r3)
#pragma unroll
                    for (int mt = 0; mt < 2; mt++)
#pragma unroll
                        for (int np = 0; np < 4; np++){
                            mma16816(acc[mt][np*2+0], a[mt], bf[np][0], bf[np][2]);
                            mma16816(acc[mt][np*2+1], a[mt], bf[np][1], bf[np][3]);
                        }
                }
            }
            __syncthreads();
        }
    }

    // ---- epilogue ----
#pragma unroll
    for (int mt = 0; mt < 2; mt++)
#pragma unroll
        for (int nt = 0; nt < 8; nt++){
            int m = m0 + mt*16 + (lane>>2);
            int n = n0 + nt*8 + (lane&3)*2;
            float* p = out + (((size_t)(b*CC + m))*HH + y)*WW + n;
            *(float2*)p = make_float2(acc[mt][nt][0], acc[mt][nt][1]);
            *(float2*)(p + (size_t)8*HH*WW) = make_float2(acc[mt][nt][2], acc[mt][nt][3]);
        }
}

// ---------------------------------------------------------------------------
extern "C" void kernel_launch(void* const* d_in, const int* in_sizes, int n_in,
                              void* d_out, int out_size){
    const float* x      = (const float*)d_in[0];
    const float* style  = (const float*)d_in[1];
    const float* weight = (const float*)d_in[2];
    const float* mod_w  = (const float*)d_in[3];
    const float* mod_b  = (const float*)d_in[4];
    float* out = (float*)d_out;

    cudaFuncSetAttribute(conv_kernel, cudaFuncAttributeMaxDynamicSharedMemorySize, SMEMSZ);

    modulate_kernel<<<BB*CC/8, 256>>>(style, mod_w, mod_b);
    weight_kernel<<<dim3(CC, BB), CC>>>(weight);
    convert_kernel<<<dim3(HH, BB), 256>>>(x);
    conv_kernel<<<dim3(HH, BB), 256, SMEMSZ>>>(out);
}